// round 9
// baseline (speedup 1.0000x reference)
#include <cuda_runtime.h>
#include <cstdint>

#define BB 4
#define SS 4096
#define DD 2048
#define RR 4
#define RFF 16
#define NROWS (BB*SS)   // 16384
#define TRM 64          // rows per block in k_main
#define MR 128          // rows per block in k_u
#define NKT 32          // K tiles (2048/64)
#define EPS 1e-6f

typedef unsigned long long u64;

// -------- device scratch (no allocation allowed) --------
// 24 folded weight vectors: 0..3 = w*V, 4..7 = U, 8..23 = w*W1
__device__ __align__(16) float g_W[24*DD];
// 25 result planes: 0 = ssq, 1..4 = u (scaled pv), 5..8 = pu, 9..24 = pw1
__device__ __align__(16) float g_planes[25*NROWS];
__device__ __align__(16) float g_h[RR*NROWS];     // planar [r][row]
__device__ __align__(16) float g_g[NROWS*RFF];    // row-major
__device__ float g_G[16];    // U^T U
__device__ float g_M[64];    // U^T (w*W1)
__device__ float g_a[RR];

// -------- packed f32x2 helpers --------
__device__ __forceinline__ u64 fma2(u64 a, u64 b, u64 c){
    u64 d; asm("fma.rn.f32x2 %0, %1, %2, %3;" : "=l"(d) : "l"(a), "l"(b), "l"(c)); return d;
}
__device__ __forceinline__ u64 add2(u64 a, u64 b){
    u64 d; asm("add.rn.f32x2 %0, %1, %2;" : "=l"(d) : "l"(a), "l"(b)); return d;
}
__device__ __forceinline__ u64 pack2(float x, float y){
    u64 r; asm("mov.b64 %0, {%1, %2};" : "=l"(r) : "f"(x), "f"(y)); return r;
}
__device__ __forceinline__ float2 unpack2(u64 p){
    float2 f; asm("mov.b64 {%0, %1}, %2;" : "=f"(f.x), "=f"(f.y) : "l"(p)); return f;
}
__device__ __forceinline__ float warp_sum(float v){
    v += __shfl_down_sync(0xffffffffu, v, 16);
    v += __shfl_down_sync(0xffffffffu, v, 8);
    v += __shfl_down_sync(0xffffffffu, v, 4);
    v += __shfl_down_sync(0xffffffffu, v, 2);
    v += __shfl_down_sync(0xffffffffu, v, 1);
    return v;
}
__device__ __forceinline__ float gelu_tanh(float x){
    float c = 0.7978845608028654f * (x + 0.044715f * x * x * x);
    return 0.5f * x * (1.0f + tanhf(c));
}

// ======================= prep (fused): fold weights + G/M dots =======================
__global__ void k_prep_all(const float* __restrict__ norm_w, const float* __restrict__ V,
                           const float* __restrict__ U, const float* __restrict__ a_logit,
                           const float* __restrict__ W1){
    int tid = threadIdx.x;
    if (blockIdx.x < 8){
        int d = blockIdx.x * 256 + tid;
        float w = norm_w[d];
        #pragma unroll
        for (int j = 0; j < 4; j++)  g_W[j*DD + d]     = w * V[d*RR + j];
        #pragma unroll
        for (int j = 0; j < 4; j++)  g_W[(4+j)*DD + d] = U[d*RR + j];
        #pragma unroll
        for (int j = 0; j < 16; j++) g_W[(8+j)*DD + d] = w * W1[d*RFF + j];
        if (blockIdx.x == 0 && tid < RR) g_a[tid] = 1.0f / (1.0f + expf(-a_logit[tid]));
    } else {
        int j = blockIdx.x - 8;   // 0..79
        float s = 0.f;
        if (j < 16){
            int k = j >> 2, q = j & 3;
            for (int d = tid; d < DD; d += 256)
                s += U[d*RR + k] * U[d*RR + q];
        } else {
            int k = (j-16) >> 4, r = (j-16) & 15;
            for (int d = tid; d < DD; d += 256)
                s += U[d*RR + k] * norm_w[d] * W1[d*RFF + r];
        }
        s = warp_sum(s);
        __shared__ float sh[8];
        if ((tid & 31) == 0) sh[tid >> 5] = s;
        __syncthreads();
        if (tid == 0){
            float t = 0.f;
            #pragma unroll
            for (int i = 0; i < 8; i++) t += sh[i];
            if (j < 16) g_G[j] = t; else g_M[j-16] = t;
        }
    }
}

// ======================= k_u: register-accumulator GEMM =======================
// 128 blocks x 256 threads. Block: rows [bid*128, +128), K-loop over 32 tiles of 64 d's.
// Thread (q = tid>>3, ks = tid&7): row-pairs 2q, 2q+1 (rows 4q..4q+3);
// d-groups g = ks and ks+8 within each tile (4 d's each).
// smem xs: [64 rowpair][66 u64] pre-paired x; wd: [24][66 u64] dup-packed weights.
__global__ void __launch_bounds__(256) k_u_gemm(const float* __restrict__ x){
    __shared__ __align__(16) u64 xs[64*66];   // 33792 B
    __shared__ __align__(16) u64 wd[24*66];   // 12672 B

    const int tid = threadIdx.x;
    const int row0 = blockIdx.x * MR;
    const int q = tid >> 3, ks = tid & 7;

    u64 acc[2][24];
    u64 sq[2];
    #pragma unroll
    for (int rp = 0; rp < 2; rp++){
        sq[rp] = 0ull;
        #pragma unroll
        for (int j = 0; j < 24; j++) acc[rp][j] = 0ull;
    }

    // prefetch registers
    float4 xa[4], xb[4];
    float wv[6];

    // ---- load tile kt into regs ----
    auto load_regs = [&](int kt){
        #pragma unroll
        for (int u = 0; u < 4; u++){
            int unit = tid + u*256;          // 0..1023
            int rp = unit >> 4, c = unit & 15;
            const float4* pA = reinterpret_cast<const float4*>(
                x + (size_t)(row0 + 2*rp)*DD + kt*64) + c;
            const float4* pB = reinterpret_cast<const float4*>(
                x + (size_t)(row0 + 2*rp + 1)*DD + kt*64) + c;
            xa[u] = *pA; xb[u] = *pB;
        }
        #pragma unroll
        for (int u = 0; u < 6; u++){
            int e = tid + u*256;             // 0..1535
            int j = e >> 6, d = e & 63;
            wv[u] = g_W[j*DD + kt*64 + d];
        }
    };

    load_regs(0);

    for (int kt = 0; kt < NKT; kt++){
        __syncthreads();   // previous compute done reading smem
        // ---- STS phase ----
        #pragma unroll
        for (int u = 0; u < 4; u++){
            int unit = tid + u*256;
            int rp = unit >> 4, c = unit & 15;
            ulonglong2* dst = reinterpret_cast<ulonglong2*>(&xs[rp*66 + c*4]);
            ulonglong2 v0; v0.x = pack2(xa[u].x, xb[u].x); v0.y = pack2(xa[u].y, xb[u].y);
            ulonglong2 v1; v1.x = pack2(xa[u].z, xb[u].z); v1.y = pack2(xa[u].w, xb[u].w);
            dst[0] = v0; dst[1] = v1;
        }
        #pragma unroll
        for (int u = 0; u < 6; u++){
            int e = tid + u*256;
            int j = e >> 6, d = e & 63;
            wd[j*66 + d] = pack2(wv[u], wv[u]);
        }
        __syncthreads();

        if (kt + 1 < NKT) load_regs(kt + 1);

        // ---- compute: two 4-d groups (g = ks, ks+8) ----
        #pragma unroll
        for (int half = 0; half < 2; half++){
            const int g4 = (ks + 8*half) * 4;
            u64 a0[4], a1[4];
            {
                ulonglong2 t0 = *reinterpret_cast<const ulonglong2*>(&xs[(2*q)*66 + g4]);
                ulonglong2 t1 = *reinterpret_cast<const ulonglong2*>(&xs[(2*q)*66 + g4 + 2]);
                a0[0]=t0.x; a0[1]=t0.y; a0[2]=t1.x; a0[3]=t1.y;
                ulonglong2 s0 = *reinterpret_cast<const ulonglong2*>(&xs[(2*q+1)*66 + g4]);
                ulonglong2 s1 = *reinterpret_cast<const ulonglong2*>(&xs[(2*q+1)*66 + g4 + 2]);
                a1[0]=s0.x; a1[1]=s0.y; a1[2]=s1.x; a1[3]=s1.y;
            }
            #pragma unroll
            for (int i = 0; i < 4; i++){
                sq[0] = fma2(a0[i], a0[i], sq[0]);
                sq[1] = fma2(a1[i], a1[i], sq[1]);
            }
            #pragma unroll
            for (int j = 0; j < 24; j++){
                const u64* bp = &wd[j*66 + g4];
                ulonglong2 b01 = *reinterpret_cast<const ulonglong2*>(bp);
                ulonglong2 b23 = *reinterpret_cast<const ulonglong2*>(bp + 2);
                acc[0][j] = fma2(a0[0], b01.x, acc[0][j]);
                acc[0][j] = fma2(a0[1], b01.y, acc[0][j]);
                acc[0][j] = fma2(a0[2], b23.x, acc[0][j]);
                acc[0][j] = fma2(a0[3], b23.y, acc[0][j]);
                acc[1][j] = fma2(a1[0], b01.x, acc[1][j]);
                acc[1][j] = fma2(a1[1], b01.y, acc[1][j]);
                acc[1][j] = fma2(a1[2], b23.x, acc[1][j]);
                acc[1][j] = fma2(a1[3], b23.y, acc[1][j]);
            }
        }
    }

    // ---- ks-reduction (butterfly over lanes differing in ks bits) ----
    #pragma unroll
    for (int s = 1; s < 8; s <<= 1){
        #pragma unroll
        for (int rp = 0; rp < 2; rp++){
            sq[rp] = add2(sq[rp], __shfl_xor_sync(0xffffffffu, sq[rp], s));
            #pragma unroll
            for (int j = 0; j < 24; j++)
                acc[rp][j] = add2(acc[rp][j], __shfl_xor_sync(0xffffffffu, acc[rp][j], s));
        }
    }

    __syncthreads();
    float* res = reinterpret_cast<float*>(xs);   // 25 x 128 staging
    if (ks == 0){
        #pragma unroll
        for (int rp = 0; rp < 2; rp++){
            int rbase = 4*q + 2*rp;
            float2 s2 = unpack2(sq[rp]);
            res[rbase] = s2.x; res[rbase+1] = s2.y;
            #pragma unroll
            for (int j = 0; j < 24; j++){
                float2 f = unpack2(acc[rp][j]);
                res[(1+j)*128 + rbase]   = f.x;
                res[(1+j)*128 + rbase+1] = f.y;
            }
        }
    }
    __syncthreads();

    for (int i = tid; i < 25*128; i += 256){
        int j = i >> 7, row = i & 127;
        float v = res[i];
        if (j >= 1 && j <= 4)
            v *= rsqrtf(res[row] * (1.0f/DD) + EPS);
        g_planes[(size_t)j*NROWS + row0 + row] = v;
    }
}

// ======================= k_scan: warp-parallel linear-recurrence scan =======================
__global__ void __launch_bounds__(256) k_scan(){
    const int b = blockIdx.x >> 2;
    const int r = blockIdx.x & 3;
    const float a = g_a[r];
    const int tid = threadIdx.x, l = tid & 31, w = tid >> 5;
    const float* u = g_planes + (size_t)(1+r)*NROWS + b*SS;

    float uu[16];
    float4* uu4 = reinterpret_cast<float4*>(uu);
    #pragma unroll
    for (int i = 0; i < 4; i++)
        uu4[i] = reinterpret_cast<const float4*>(u)[tid*4 + i];

    float f = 0.f;
    #pragma unroll
    for (int i = 0; i < 16; i++) f = a*f + uu[i];

    float A = a; A *= A; A *= A; A *= A; A *= A;   // a^16

    float I = f, As = A;
    #pragma unroll
    for (int st = 0; st < 5; st++){
        float gg = __shfl_up_sync(0xffffffffu, I, 1 << st);
        if (l >= (1 << st)) I += As * gg;
        As *= As;
    }

    __shared__ float Tw[8], Ww[8];
    if (l == 31) Tw[w] = I;
    __syncthreads();
    if (tid == 0){
        float A32 = A;
        #pragma unroll
        for (int k = 0; k < 5; k++) A32 *= A32;  // a^512
        float c = 0.f;
        #pragma unroll
        for (int j = 0; j < 8; j++){ Ww[j] = c; c = A32*c + Tw[j]; }
    }
    __syncthreads();

    float Al = 1.f, p = A;
    #pragma unroll
    for (int bit = 0; bit < 5; bit++){ if ((l >> bit) & 1) Al *= p; p *= p; }
    float Iprev = __shfl_up_sync(0xffffffffu, I, 1);
    float c = ((l == 0) ? 0.f : Iprev) + Al * Ww[w];

    float* hh = g_h + r*NROWS + b*SS;
    float h = c;
    float ho[16];
    #pragma unroll
    for (int i = 0; i < 16; i++){ h = a*h + uu[i]; ho[i] = h; }
    float4* ho4 = reinterpret_cast<float4*>(ho);
    #pragma unroll
    for (int i = 0; i < 4; i++)
        reinterpret_cast<float4*>(hh)[tid*4 + i] = ho4[i];
}

// ======================= k_post: per-row scale1, t, gelu =======================
__global__ void __launch_bounds__(256) k_post(){
    __shared__ float sG[16], sM[64];
    int tid = threadIdx.x;
    if (tid < 16) sG[tid] = g_G[tid];
    if (tid < 64) sM[tid] = g_M[tid];
    __syncthreads();

    int row = blockIdx.x * 256 + tid;
    float h[4], p[4];
    #pragma unroll
    for (int k = 0; k < 4; k++) h[k] = g_h[k*NROWS + row];
    #pragma unroll
    for (int k = 0; k < 4; k++) p[k] = g_planes[(size_t)(5+k)*NROWS + row];

    float s1 = g_planes[row];   // plane 0 = ssq
    #pragma unroll
    for (int k = 0; k < 4; k++) s1 += 2.0f * h[k] * p[k];
    #pragma unroll
    for (int k = 0; k < 4; k++)
        #pragma unroll
        for (int qq = 0; qq < 4; qq++) s1 += h[k] * h[qq] * sG[k*4+qq];
    float scale = rsqrtf(s1 * (1.0f/DD) + EPS);

    #pragma unroll
    for (int r = 0; r < RFF; r++){
        float t = g_planes[(size_t)(9+r)*NROWS + row];
        #pragma unroll
        for (int k = 0; k < 4; k++) t += h[k] * sM[k*16 + r];
        g_g[(size_t)row*RFF + r] = gelu_tanh(t * scale);
    }
}

// ======================= k_main: out = x + U h + g @ W2 =======================
// 256 threads, 2 CTA/SM; thread owns one ulonglong2 (4 floats); 64 rows/block.
// grid = (NROWS/TRM, 2)
__global__ void __launch_bounds__(256, 2) k_main(const float* __restrict__ x,
                                                 const float* __restrict__ W2,
                                                 float* __restrict__ out){
    const int row0 = blockIdx.x * TRM;
    const int tid  = threadIdx.x;
    const int q    = blockIdx.y * 256 + tid;   // ulonglong2 index within row (0..511)

    ulonglong2 ut[4], w2[16];
    #pragma unroll
    for (int k = 0; k < 4; k++)
        ut[k] = reinterpret_cast<const ulonglong2*>(g_W + (4+k)*DD)[q];
    #pragma unroll
    for (int r = 0; r < RFF; r++)
        w2[r] = reinterpret_cast<const ulonglong2*>(W2)[r*(DD/4) + q];

    // scalars pre-packed as duplicated f32x2 pairs: [h0..h3, g0..g15] per row
    __shared__ __align__(16) u64 hs2[TRM][20];
    for (int i = tid; i < TRM*20; i += 256){
        int row = i / 20, j = i % 20;
        float v = (j < 4) ? g_h[j*NROWS + row0 + row]
                          : g_g[(size_t)(row0+row)*RFF + (j-4)];
        hs2[row][j] = pack2(v, v);
    }
    __syncthreads();

    const ulonglong2* xr = reinterpret_cast<const ulonglong2*>(x) + (size_t)row0*(DD/4) + q;
    ulonglong2*       op = reinterpret_cast<ulonglong2*>(out)     + (size_t)row0*(DD/4) + q;

    ulonglong2 xa = xr[0];
    ulonglong2 xb = xr[DD/4];
    #pragma unroll 4
    for (int row = 0; row < TRM; row++){
        ulonglong2 xn = xb;
        if (row + 2 < TRM) xn = xr[(size_t)(row+2)*(DD/4)];

        u64 a0 = xa.x, a1 = xa.y, b0 = 0ull, b1 = 0ull;
        const ulonglong2* s2 = reinterpret_cast<const ulonglong2*>(&hs2[row][0]);
        #pragma unroll
        for (int i = 0; i < 10; i++){
            ulonglong2 sp = s2[i];           // two packed scalars (LDS.128 broadcast)
            const int j0 = 2*i, j1 = 2*i + 1;
            u64 w0x = (j0 < 4) ? ut[j0].x : w2[j0-4].x;
            u64 w0y = (j0 < 4) ? ut[j0].y : w2[j0-4].y;
            u64 w1x = (j1 < 4) ? ut[j1].x : w2[j1-4].x;
            u64 w1y = (j1 < 4) ? ut[j1].y : w2[j1-4].y;
            a0 = fma2(sp.x, w0x, a0);  a1 = fma2(sp.x, w0y, a1);
            b0 = fma2(sp.y, w1x, b0);  b1 = fma2(sp.y, w1y, b1);
        }
        ulonglong2 o;
        o.x = add2(a0, b0);
        o.y = add2(a1, b1);
        op[(size_t)row*(DD/4)] = o;
        xa = xb; xb = xn;
    }
}

// ======================= launch =======================
extern "C" void kernel_launch(void* const* d_in, const int* in_sizes, int n_in,
                              void* d_out, int out_size){
    const float* x       = (const float*)d_in[0];
    const float* norm_w  = (const float*)d_in[1];
    const float* V       = (const float*)d_in[2];
    const float* U       = (const float*)d_in[3];
    const float* a_logit = (const float*)d_in[4];
    const float* W1      = (const float*)d_in[5];
    const float* W2      = (const float*)d_in[6];
    float* out = (float*)d_out;

    k_prep_all<<<88, 256>>>(norm_w, V, U, a_logit, W1);
    k_u_gemm  <<<NROWS/MR, 256>>>(x);
    k_scan    <<<BB*RR, 256>>>();
    k_post    <<<NROWS/256, 256>>>();
    dim3 gm(NROWS/TRM, 2);
    k_main    <<<gm, 256>>>(x, W2, out);
}

// round 10
// speedup vs baseline: 1.2481x; 1.2481x over previous
#include <cuda_runtime.h>
#include <cstdint>

#define BB 4
#define SS 4096
#define DD 2048
#define RR 4
#define RFF 16
#define NROWS (BB*SS)   // 16384
#define TRU 8           // rows per block in k_u
#define TRM 64          // rows per block in k_main
#define EPS 1e-6f

typedef unsigned long long u64;

// -------- device scratch (no allocation allowed) --------
__device__ __align__(16) float g_ssq[NROWS];
__device__ __align__(16) float g_u  [RR*NROWS];   // planar [r][row], pre-scaled by rmsnorm
__device__ __align__(16) float g_pu [NROWS*RR];   // row-major
__device__ __align__(16) float g_pw1[NROWS*RFF];  // row-major
__device__ __align__(16) float g_h  [RR*NROWS];   // planar [r][row]
__device__ __align__(16) float g_g  [NROWS*RFF];  // row-major
__device__ __align__(16) float g_Vt [RR*DD];      // w*V transposed
__device__ __align__(16) float g_Ut [RR*DD];      // U transposed
__device__ __align__(16) float g_W1t[RFF*DD];     // w*W1 transposed
__device__ float g_G[16];    // U^T U
__device__ float g_M[64];    // U^T (w*W1)
__device__ float g_a[RR];

// -------- packed f32x2 helpers --------
__device__ __forceinline__ u64 fma2(u64 a, u64 b, u64 c){
    u64 d; asm("fma.rn.f32x2 %0, %1, %2, %3;" : "=l"(d) : "l"(a), "l"(b), "l"(c)); return d;
}
__device__ __forceinline__ u64 add2(u64 a, u64 b){
    u64 d; asm("add.rn.f32x2 %0, %1, %2;" : "=l"(d) : "l"(a), "l"(b)); return d;
}
__device__ __forceinline__ u64 pack2(float x, float y){
    u64 r; asm("mov.b64 %0, {%1, %2};" : "=l"(r) : "f"(x), "f"(y)); return r;
}
__device__ __forceinline__ float2 unpack2(u64 p){
    float2 f; asm("mov.b64 {%0, %1}, %2;" : "=f"(f.x), "=f"(f.y) : "l"(p)); return f;
}
__device__ __forceinline__ float warp_sum(float v){
    v += __shfl_down_sync(0xffffffffu, v, 16);
    v += __shfl_down_sync(0xffffffffu, v, 8);
    v += __shfl_down_sync(0xffffffffu, v, 4);
    v += __shfl_down_sync(0xffffffffu, v, 2);
    v += __shfl_down_sync(0xffffffffu, v, 1);
    return v;
}
// butterfly reduce-scatter: after call, each lane holds warp-total of
// value index (lane & (N-1)). N power of 2.
template<int N>
__device__ __forceinline__ float rs_reduce(float (&v)[N], int lane){
    #pragma unroll
    for (int s = N/2; s >= 1; s >>= 1){
        bool up = (lane & s) != 0;
        #pragma unroll
        for (int i = 0; i < s; i++){
            float send = up ? v[i] : v[i+s];
            float keep = up ? v[i+s] : v[i];
            v[i] = keep + __shfl_xor_sync(0xffffffffu, send, s);
        }
    }
    float r = v[0];
    #pragma unroll
    for (int s = N; s < 32; s <<= 1)
        r += __shfl_xor_sync(0xffffffffu, r, s);
    return r;
}
__device__ __forceinline__ float gelu_tanh(float x){
    float c = 0.7978845608028654f * (x + 0.044715f * x * x * x);
    return 0.5f * x * (1.0f + tanhf(c));
}

// ======================= prep (fused): transpose/fold + G/M dots =======================
__global__ void k_prep_all(const float* __restrict__ norm_w, const float* __restrict__ V,
                           const float* __restrict__ U, const float* __restrict__ a_logit,
                           const float* __restrict__ W1){
    int tid = threadIdx.x;
    if (blockIdx.x < 8){
        int d = blockIdx.x * 256 + tid;
        float w = norm_w[d];
        #pragma unroll
        for (int r = 0; r < RR; r++){
            g_Vt[r*DD + d] = w * V[d*RR + r];
            g_Ut[r*DD + d] = U[d*RR + r];
        }
        #pragma unroll
        for (int r = 0; r < RFF; r++)
            g_W1t[r*DD + d] = w * W1[d*RFF + r];
        if (blockIdx.x == 0 && tid < RR) g_a[tid] = 1.0f / (1.0f + expf(-a_logit[tid]));
    } else {
        int j = blockIdx.x - 8;   // 0..79
        float s = 0.f;
        if (j < 16){
            int k = j >> 2, q = j & 3;
            for (int d = tid; d < DD; d += 256)
                s += U[d*RR + k] * U[d*RR + q];
        } else {
            int k = (j-16) >> 4, r = (j-16) & 15;
            for (int d = tid; d < DD; d += 256)
                s += U[d*RR + k] * norm_w[d] * W1[d*RFF + r];
        }
        s = warp_sum(s);
        __shared__ float sh[8];
        if ((tid & 31) == 0) sh[tid >> 5] = s;
        __syncthreads();
        if (tid == 0){
            float t = 0.f;
            #pragma unroll
            for (int i = 0; i < 8; i++) t += sh[i];
            if (j < 16) g_G[j] = t; else g_M[j-16] = t;
        }
    }
}

// ======================= k_u: 25 dots per row over x (R7 version) =======================
__global__ void __launch_bounds__(512) k_u(const float* __restrict__ x){
    const int row0 = blockIdx.x * TRU;
    const int tid = threadIdx.x;
    const int w = tid >> 5, l = tid & 31;
    __shared__ float sred[TRU][25][17];
    __shared__ float tot[TRU][25];

    ulonglong2 xp[TRU];
    #pragma unroll
    for (int row = 0; row < TRU; row++)
        xp[row] = reinterpret_cast<const ulonglong2*>(x)[(size_t)(row0+row)*(DD/4) + tid];

    // ---- pass A: ssq + V(4) + U(4) -> slots 0..8 ----
    {
        ulonglong2 wp[8];
        #pragma unroll
        for (int r = 0; r < 4; r++){
            wp[r]   = reinterpret_cast<const ulonglong2*>(g_Vt)[r*(DD/4) + tid];
            wp[4+r] = reinterpret_cast<const ulonglong2*>(g_Ut)[r*(DD/4) + tid];
        }
        #pragma unroll
        for (int row = 0; row < TRU; row++){
            float2 fs = unpack2(fma2(xp[row].x, xp[row].x, fma2(xp[row].y, xp[row].y, 0ull)));
            float ss = warp_sum(fs.x + fs.y);
            float v[8];
            #pragma unroll
            for (int j = 0; j < 8; j++){
                float2 f = unpack2(fma2(xp[row].x, wp[j].x, fma2(xp[row].y, wp[j].y, 0ull)));
                v[j] = f.x + f.y;
            }
            float rv = rs_reduce<8>(v, l);
            if (l == 0) sred[row][0][w] = ss;
            if (l < 8)  sred[row][1+l][w] = rv;
        }
    }
    __syncthreads();   // scheduling fence: keep weight-pass register sets disjoint

    // ---- passes B,C: W1 ranks, 8 at a time -> slots 9..24 ----
    #pragma unroll
    for (int half = 0; half < 2; half++){
        ulonglong2 wp[8];
        #pragma unroll
        for (int r = 0; r < 8; r++)
            wp[r] = reinterpret_cast<const ulonglong2*>(g_W1t)[(half*8+r)*(DD/4) + tid];
        #pragma unroll
        for (int row = 0; row < TRU; row++){
            float v[8];
            #pragma unroll
            for (int j = 0; j < 8; j++){
                float2 f = unpack2(fma2(xp[row].x, wp[j].x, fma2(xp[row].y, wp[j].y, 0ull)));
                v[j] = f.x + f.y;
            }
            float rv = rs_reduce<8>(v, l);
            if (l < 8) sred[row][9 + half*8 + l][w] = rv;
        }
        __syncthreads();
    }

    if (tid < TRU*25){
        int row = tid / 25, val = tid % 25;
        float s = 0.f;
        #pragma unroll
        for (int ww = 0; ww < 16; ww++) s += sred[row][val][ww];
        tot[row][val] = s;
    }
    __syncthreads();
    if (tid < TRU*25){
        int row = tid / 25, val = tid % 25;
        int gr = row0 + row;
        float s = tot[row][val];
        if (val == 0) g_ssq[gr] = s;
        else if (val < 5){
            float scale = rsqrtf(tot[row][0] * (1.0f/DD) + EPS);
            g_u[(val-1)*NROWS + gr] = scale * s;
        }
        else if (val < 9) g_pu[(size_t)gr*RR + (val-5)] = s;
        else              g_pw1[(size_t)gr*RFF + (val-9)] = s;
    }
}

// ======================= k_scan: warp-parallel linear-recurrence scan =======================
__global__ void __launch_bounds__(256) k_scan(){
    const int b = blockIdx.x >> 2;
    const int r = blockIdx.x & 3;
    const float a = g_a[r];
    const int tid = threadIdx.x, l = tid & 31, w = tid >> 5;
    const float* u = g_u + r*NROWS + b*SS;

    float uu[16];
    float4* uu4 = reinterpret_cast<float4*>(uu);
    #pragma unroll
    for (int i = 0; i < 4; i++)
        uu4[i] = reinterpret_cast<const float4*>(u)[tid*4 + i];

    float f = 0.f;
    #pragma unroll
    for (int i = 0; i < 16; i++) f = a*f + uu[i];

    float A = a; A *= A; A *= A; A *= A; A *= A;   // a^16

    float I = f, As = A;
    #pragma unroll
    for (int st = 0; st < 5; st++){
        float gg = __shfl_up_sync(0xffffffffu, I, 1 << st);
        if (l >= (1 << st)) I += As * gg;
        As *= As;
    }

    __shared__ float Tw[8], Ww[8];
    if (l == 31) Tw[w] = I;
    __syncthreads();
    if (tid == 0){
        float A32 = A;
        #pragma unroll
        for (int k = 0; k < 5; k++) A32 *= A32;  // a^512
        float c = 0.f;
        #pragma unroll
        for (int j = 0; j < 8; j++){ Ww[j] = c; c = A32*c + Tw[j]; }
    }
    __syncthreads();

    float Al = 1.f, p = A;
    #pragma unroll
    for (int bit = 0; bit < 5; bit++){ if ((l >> bit) & 1) Al *= p; p *= p; }
    float Iprev = __shfl_up_sync(0xffffffffu, I, 1);
    float c = ((l == 0) ? 0.f : Iprev) + Al * Ww[w];

    float* hh = g_h + r*NROWS + b*SS;
    float h = c;
    float ho[16];
    #pragma unroll
    for (int i = 0; i < 16; i++){ h = a*h + uu[i]; ho[i] = h; }
    float4* ho4 = reinterpret_cast<float4*>(ho);
    #pragma unroll
    for (int i = 0; i < 4; i++)
        reinterpret_cast<float4*>(hh)[tid*4 + i] = ho4[i];
}

// ======================= k_post: per-row scale1, t, gelu =======================
__global__ void __launch_bounds__(256) k_post(){
    __shared__ float sG[16], sM[64];
    int tid = threadIdx.x;
    if (tid < 16) sG[tid] = g_G[tid];
    if (tid < 64) sM[tid] = g_M[tid];
    __syncthreads();

    int row = blockIdx.x * 256 + tid;
    float h[4], p[4];
    #pragma unroll
    for (int k = 0; k < 4; k++) h[k] = g_h[k*NROWS + row];
    float4 p4 = reinterpret_cast<const float4*>(g_pu)[row];
    p[0]=p4.x; p[1]=p4.y; p[2]=p4.z; p[3]=p4.w;

    float s1 = g_ssq[row];
    #pragma unroll
    for (int k = 0; k < 4; k++) s1 += 2.0f * h[k] * p[k];
    #pragma unroll
    for (int k = 0; k < 4; k++)
        #pragma unroll
        for (int q = 0; q < 4; q++) s1 += h[k] * h[q] * sG[k*4+q];
    float scale = rsqrtf(s1 * (1.0f/DD) + EPS);

    #pragma unroll
    for (int r = 0; r < RFF; r++){
        float t = g_pw1[(size_t)row*RFF + r];
        #pragma unroll
        for (int k = 0; k < 4; k++) t += h[k] * sM[k*16 + r];
        g_g[(size_t)row*RFF + r] = gelu_tanh(t * scale);
    }
}

// ======================= k_main: out = x + U h + g @ W2 (TRM=64) =======================
// 256 threads, 2 CTA/SM; thread owns one ulonglong2 (4 floats); 64 rows/block.
// grid = (NROWS/TRM, 2)
__global__ void __launch_bounds__(256, 2) k_main(const float* __restrict__ x,
                                                 const float* __restrict__ W2,
                                                 float* __restrict__ out){
    const int row0 = blockIdx.x * TRM;
    const int tid  = threadIdx.x;
    const int q    = blockIdx.y * 256 + tid;   // ulonglong2 index within row (0..511)

    ulonglong2 ut[4], w2[16];
    #pragma unroll
    for (int k = 0; k < 4; k++)
        ut[k] = reinterpret_cast<const ulonglong2*>(g_Ut)[k*(DD/4) + q];
    #pragma unroll
    for (int r = 0; r < RFF; r++)
        w2[r] = reinterpret_cast<const ulonglong2*>(W2)[r*(DD/4) + q];

    // scalars pre-packed as duplicated f32x2 pairs: [h0..h3, g0..g15] per row
    __shared__ __align__(16) u64 hs2[TRM][20];
    for (int i = tid; i < TRM*20; i += 256){
        int row = i / 20, j = i % 20;
        float v = (j < 4) ? g_h[j*NROWS + row0 + row]
                          : g_g[(size_t)(row0+row)*RFF + (j-4)];
        hs2[row][j] = pack2(v, v);
    }
    __syncthreads();

    const ulonglong2* xr = reinterpret_cast<const ulonglong2*>(x) + (size_t)row0*(DD/4) + q;
    ulonglong2*       op = reinterpret_cast<ulonglong2*>(out)     + (size_t)row0*(DD/4) + q;

    ulonglong2 xa = xr[0];
    ulonglong2 xb = xr[DD/4];
    #pragma unroll 4
    for (int row = 0; row < TRM; row++){
        ulonglong2 xn = xb;
        if (row + 2 < TRM) xn = xr[(size_t)(row+2)*(DD/4)];

        u64 a0 = xa.x, a1 = xa.y, b0 = 0ull, b1 = 0ull;
        const ulonglong2* s2 = reinterpret_cast<const ulonglong2*>(&hs2[row][0]);
        #pragma unroll
        for (int i = 0; i < 10; i++){
            ulonglong2 sp = s2[i];           // two packed scalars (LDS.128 broadcast)
            const int j0 = 2*i, j1 = 2*i + 1;
            u64 w0x = (j0 < 4) ? ut[j0].x : w2[j0-4].x;
            u64 w0y = (j0 < 4) ? ut[j0].y : w2[j0-4].y;
            u64 w1x = (j1 < 4) ? ut[j1].x : w2[j1-4].x;
            u64 w1y = (j1 < 4) ? ut[j1].y : w2[j1-4].y;
            a0 = fma2(sp.x, w0x, a0);  a1 = fma2(sp.x, w0y, a1);
            b0 = fma2(sp.y, w1x, b0);  b1 = fma2(sp.y, w1y, b1);
        }
        ulonglong2 o;
        o.x = add2(a0, b0);
        o.y = add2(a1, b1);
        op[(size_t)row*(DD/4)] = o;
        xa = xb; xb = xn;
    }
}

// ======================= launch =======================
extern "C" void kernel_launch(void* const* d_in, const int* in_sizes, int n_in,
                              void* d_out, int out_size){
    const float* x       = (const float*)d_in[0];
    const float* norm_w  = (const float*)d_in[1];
    const float* V       = (const float*)d_in[2];
    const float* U       = (const float*)d_in[3];
    const float* a_logit = (const float*)d_in[4];
    const float* W1      = (const float*)d_in[5];
    const float* W2      = (const float*)d_in[6];
    float* out = (float*)d_out;

    k_prep_all<<<88, 256>>>(norm_w, V, U, a_logit, W1);
    k_u    <<<NROWS/TRU, 512>>>(x);
    k_scan <<<BB*RR, 256>>>();
    k_post <<<NROWS/256, 256>>>();
    dim3 gm(NROWS/TRM, 2);
    k_main <<<gm, 256>>>(x, W2, out);
}

// round 11
// speedup vs baseline: 1.3089x; 1.0487x over previous
#include <cuda_runtime.h>
#include <cstdint>

#define BB 4
#define SS 4096
#define DD 2048
#define RR 4
#define RFF 16
#define NROWS (BB*SS)   // 16384
#define TRU 16          // rows per block in k_u
#define TRM 16          // rows per block in k_main
#define EPS 1e-6f

typedef unsigned long long u64;

// -------- device scratch (no allocation allowed) --------
__device__ __align__(16) float g_ssq[NROWS];
__device__ __align__(16) float g_u  [RR*NROWS];   // planar [r][row], pre-scaled by rmsnorm
__device__ __align__(16) float g_pu [NROWS*RR];   // row-major
__device__ __align__(16) float g_pw1[NROWS*RFF];  // row-major
__device__ __align__(16) float g_h  [RR*NROWS];   // planar [r][row]
__device__ __align__(16) float g_g  [NROWS*RFF];  // row-major
__device__ __align__(16) float g_Vt [RR*DD];      // w*V transposed
__device__ __align__(16) float g_Ut [RR*DD];      // U transposed
__device__ __align__(16) float g_W1t[RFF*DD];     // w*W1 transposed
__device__ float g_G[16];    // U^T U
__device__ float g_M[64];    // U^T (w*W1)
__device__ float g_a[RR];

// -------- packed f32x2 helpers --------
__device__ __forceinline__ u64 fma2(u64 a, u64 b, u64 c){
    u64 d; asm("fma.rn.f32x2 %0, %1, %2, %3;" : "=l"(d) : "l"(a), "l"(b), "l"(c)); return d;
}
__device__ __forceinline__ u64 add2(u64 a, u64 b){
    u64 d; asm("add.rn.f32x2 %0, %1, %2;" : "=l"(d) : "l"(a), "l"(b)); return d;
}
__device__ __forceinline__ u64 pack2(float x, float y){
    u64 r; asm("mov.b64 %0, {%1, %2};" : "=l"(r) : "f"(x), "f"(y)); return r;
}
__device__ __forceinline__ float2 unpack2(u64 p){
    float2 f; asm("mov.b64 {%0, %1}, %2;" : "=f"(f.x), "=f"(f.y) : "l"(p)); return f;
}
__device__ __forceinline__ float warp_sum(float v){
    v += __shfl_down_sync(0xffffffffu, v, 16);
    v += __shfl_down_sync(0xffffffffu, v, 8);
    v += __shfl_down_sync(0xffffffffu, v, 4);
    v += __shfl_down_sync(0xffffffffu, v, 2);
    v += __shfl_down_sync(0xffffffffu, v, 1);
    return v;
}
// butterfly reduce-scatter: after call, each lane holds warp-total of
// value index (lane & (N-1)). N power of 2.
template<int N>
__device__ __forceinline__ float rs_reduce(float (&v)[N], int lane){
    #pragma unroll
    for (int s = N/2; s >= 1; s >>= 1){
        bool up = (lane & s) != 0;
        #pragma unroll
        for (int i = 0; i < s; i++){
            float send = up ? v[i] : v[i+s];
            float keep = up ? v[i+s] : v[i];
            v[i] = keep + __shfl_xor_sync(0xffffffffu, send, s);
        }
    }
    float r = v[0];
    #pragma unroll
    for (int s = N; s < 32; s <<= 1)
        r += __shfl_xor_sync(0xffffffffu, r, s);
    return r;
}
__device__ __forceinline__ float gelu_tanh(float x){
    float c = 0.7978845608028654f * (x + 0.044715f * x * x * x);
    return 0.5f * x * (1.0f + tanhf(c));
}

// ======================= prep (fused): transpose/fold + G/M dots =======================
__global__ void k_prep_all(const float* __restrict__ norm_w, const float* __restrict__ V,
                           const float* __restrict__ U, const float* __restrict__ a_logit,
                           const float* __restrict__ W1){
    int tid = threadIdx.x;
    if (blockIdx.x < 8){
        int d = blockIdx.x * 256 + tid;
        float w = norm_w[d];
        #pragma unroll
        for (int r = 0; r < RR; r++){
            g_Vt[r*DD + d] = w * V[d*RR + r];
            g_Ut[r*DD + d] = U[d*RR + r];
        }
        #pragma unroll
        for (int r = 0; r < RFF; r++)
            g_W1t[r*DD + d] = w * W1[d*RFF + r];
        if (blockIdx.x == 0 && tid < RR) g_a[tid] = 1.0f / (1.0f + expf(-a_logit[tid]));
    } else {
        int j = blockIdx.x - 8;   // 0..79
        float s = 0.f;
        if (j < 16){
            int k = j >> 2, q = j & 3;
            for (int d = tid; d < DD; d += 256)
                s += U[d*RR + k] * U[d*RR + q];
        } else {
            int k = (j-16) >> 4, r = (j-16) & 15;
            for (int d = tid; d < DD; d += 256)
                s += U[d*RR + k] * norm_w[d] * W1[d*RFF + r];
        }
        s = warp_sum(s);
        __shared__ float sh[8];
        if ((tid & 31) == 0) sh[tid >> 5] = s;
        __syncthreads();
        if (tid == 0){
            float t = 0.f;
            #pragma unroll
            for (int i = 0; i < 8; i++) t += sh[i];
            if (j < 16) g_G[j] = t; else g_M[j-16] = t;
        }
    }
}

// ======================= k_u: 25 dots per row over x (TRU=16) =======================
__global__ void __launch_bounds__(512) k_u(const float* __restrict__ x){
    const int row0 = blockIdx.x * TRU;
    const int tid = threadIdx.x;
    const int w = tid >> 5, l = tid & 31;
    __shared__ float sred[TRU][25][17];
    __shared__ float tot[TRU][25];

    ulonglong2 xp[TRU];
    #pragma unroll
    for (int row = 0; row < TRU; row++)
        xp[row] = reinterpret_cast<const ulonglong2*>(x)[(size_t)(row0+row)*(DD/4) + tid];

    // ---- pass A: ssq + V(4) + U(4) -> slots 0..8 ----
    {
        ulonglong2 wp[8];
        #pragma unroll
        for (int r = 0; r < 4; r++){
            wp[r]   = reinterpret_cast<const ulonglong2*>(g_Vt)[r*(DD/4) + tid];
            wp[4+r] = reinterpret_cast<const ulonglong2*>(g_Ut)[r*(DD/4) + tid];
        }
        #pragma unroll
        for (int row = 0; row < TRU; row++){
            float2 fs = unpack2(fma2(xp[row].x, xp[row].x, fma2(xp[row].y, xp[row].y, 0ull)));
            float ss = warp_sum(fs.x + fs.y);
            float v[8];
            #pragma unroll
            for (int j = 0; j < 8; j++){
                float2 f = unpack2(fma2(xp[row].x, wp[j].x, fma2(xp[row].y, wp[j].y, 0ull)));
                v[j] = f.x + f.y;
            }
            float rv = rs_reduce<8>(v, l);
            if (l == 0) sred[row][0][w] = ss;
            if (l < 8)  sred[row][1+l][w] = rv;
        }
    }
    __syncthreads();   // scheduling fence: keep weight-pass register sets disjoint

    // ---- passes B,C: W1 ranks, 8 at a time -> slots 9..24 ----
    #pragma unroll
    for (int half = 0; half < 2; half++){
        ulonglong2 wp[8];
        #pragma unroll
        for (int r = 0; r < 8; r++)
            wp[r] = reinterpret_cast<const ulonglong2*>(g_W1t)[(half*8+r)*(DD/4) + tid];
        #pragma unroll
        for (int row = 0; row < TRU; row++){
            float v[8];
            #pragma unroll
            for (int j = 0; j < 8; j++){
                float2 f = unpack2(fma2(xp[row].x, wp[j].x, fma2(xp[row].y, wp[j].y, 0ull)));
                v[j] = f.x + f.y;
            }
            float rv = rs_reduce<8>(v, l);
            if (l < 8) sred[row][9 + half*8 + l][w] = rv;
        }
        __syncthreads();
    }

    if (tid < TRU*25){
        int row = tid / 25, val = tid % 25;
        float s = 0.f;
        #pragma unroll
        for (int ww = 0; ww < 16; ww++) s += sred[row][val][ww];
        tot[row][val] = s;
    }
    __syncthreads();
    if (tid < TRU*25){
        int row = tid / 25, val = tid % 25;
        int gr = row0 + row;
        float s = tot[row][val];
        if (val == 0) g_ssq[gr] = s;
        else if (val < 5){
            float scale = rsqrtf(tot[row][0] * (1.0f/DD) + EPS);
            g_u[(val-1)*NROWS + gr] = scale * s;
        }
        else if (val < 9) g_pu[(size_t)gr*RR + (val-5)] = s;
        else              g_pw1[(size_t)gr*RFF + (val-9)] = s;
    }
}

// ======================= k_scan: warp-parallel linear-recurrence scan =======================
__global__ void __launch_bounds__(256) k_scan(){
    const int b = blockIdx.x >> 2;
    const int r = blockIdx.x & 3;
    const float a = g_a[r];
    const int tid = threadIdx.x, l = tid & 31, w = tid >> 5;
    const float* u = g_u + r*NROWS + b*SS;

    float uu[16];
    float4* uu4 = reinterpret_cast<float4*>(uu);
    #pragma unroll
    for (int i = 0; i < 4; i++)
        uu4[i] = reinterpret_cast<const float4*>(u)[tid*4 + i];

    float f = 0.f;
    #pragma unroll
    for (int i = 0; i < 16; i++) f = a*f + uu[i];

    float A = a; A *= A; A *= A; A *= A; A *= A;   // a^16

    float I = f, As = A;
    #pragma unroll
    for (int st = 0; st < 5; st++){
        float gg = __shfl_up_sync(0xffffffffu, I, 1 << st);
        if (l >= (1 << st)) I += As * gg;
        As *= As;
    }

    __shared__ float Tw[8], Ww[8];
    if (l == 31) Tw[w] = I;
    __syncthreads();
    if (tid == 0){
        float A32 = A;
        #pragma unroll
        for (int k = 0; k < 5; k++) A32 *= A32;  // a^512
        float c = 0.f;
        #pragma unroll
        for (int j = 0; j < 8; j++){ Ww[j] = c; c = A32*c + Tw[j]; }
    }
    __syncthreads();

    float Al = 1.f, p = A;
    #pragma unroll
    for (int bit = 0; bit < 5; bit++){ if ((l >> bit) & 1) Al *= p; p *= p; }
    float Iprev = __shfl_up_sync(0xffffffffu, I, 1);
    float c = ((l == 0) ? 0.f : Iprev) + Al * Ww[w];

    float* hh = g_h + r*NROWS + b*SS;
    float h = c;
    float ho[16];
    #pragma unroll
    for (int i = 0; i < 16; i++){ h = a*h + uu[i]; ho[i] = h; }
    float4* ho4 = reinterpret_cast<float4*>(ho);
    #pragma unroll
    for (int i = 0; i < 4; i++)
        reinterpret_cast<float4*>(hh)[tid*4 + i] = ho4[i];
}

// ======================= k_post: per-row scale1, t, gelu =======================
__global__ void __launch_bounds__(256) k_post(){
    __shared__ float sG[16], sM[64];
    int tid = threadIdx.x;
    if (tid < 16) sG[tid] = g_G[tid];
    if (tid < 64) sM[tid] = g_M[tid];
    __syncthreads();

    int row = blockIdx.x * 256 + tid;
    float h[4], p[4];
    #pragma unroll
    for (int k = 0; k < 4; k++) h[k] = g_h[k*NROWS + row];
    float4 p4 = reinterpret_cast<const float4*>(g_pu)[row];
    p[0]=p4.x; p[1]=p4.y; p[2]=p4.z; p[3]=p4.w;

    float s1 = g_ssq[row];
    #pragma unroll
    for (int k = 0; k < 4; k++) s1 += 2.0f * h[k] * p[k];
    #pragma unroll
    for (int k = 0; k < 4; k++)
        #pragma unroll
        for (int q = 0; q < 4; q++) s1 += h[k] * h[q] * sG[k*4+q];
    float scale = rsqrtf(s1 * (1.0f/DD) + EPS);

    #pragma unroll
    for (int r = 0; r < RFF; r++){
        float t = g_pw1[(size_t)row*RFF + r];
        #pragma unroll
        for (int k = 0; k < 4; k++) t += h[k] * sM[k*16 + r];
        g_g[(size_t)row*RFF + r] = gelu_tanh(t * scale);
    }
}

// ======================= k_main: out = x + U h + g @ W2 (R7 exact, TRM=16) =======================
// 256 threads, 2 CTA/SM; thread owns one ulonglong2 (4 floats); 16 rows/block.
// grid = (NROWS/TRM, 2)
__global__ void __launch_bounds__(256, 2) k_main(const float* __restrict__ x,
                                                 const float* __restrict__ W2,
                                                 float* __restrict__ out){
    const int row0 = blockIdx.x * TRM;
    const int tid  = threadIdx.x;
    const int q    = blockIdx.y * 256 + tid;   // ulonglong2 index within row (0..511)

    ulonglong2 ut[4], w2[16];
    #pragma unroll
    for (int k = 0; k < 4; k++)
        ut[k] = reinterpret_cast<const ulonglong2*>(g_Ut)[k*(DD/4) + q];
    #pragma unroll
    for (int r = 0; r < RFF; r++)
        w2[r] = reinterpret_cast<const ulonglong2*>(W2)[r*(DD/4) + q];

    __shared__ __align__(16) float hs[TRM][20];
    for (int i = tid; i < TRM*20; i += 256){
        int row = i / 20, j = i % 20;
        hs[row][j] = (j < 4) ? g_h[j*NROWS + row0 + row]
                             : g_g[(size_t)(row0+row)*RFF + (j-4)];
    }
    __syncthreads();

    const ulonglong2* xr = reinterpret_cast<const ulonglong2*>(x) + (size_t)row0*(DD/4) + q;
    ulonglong2*       op = reinterpret_cast<ulonglong2*>(out)     + (size_t)row0*(DD/4) + q;

    ulonglong2 xa = xr[0];
    #pragma unroll
    for (int row = 0; row < TRM; row++){
        ulonglong2 xn = xa;
        if (row + 1 < TRM) xn = xr[(size_t)(row+1)*(DD/4)];

        float sc[20];
        float4* sc4 = reinterpret_cast<float4*>(sc);
        const float4* hp = reinterpret_cast<const float4*>(&hs[row][0]);
        #pragma unroll
        for (int i = 0; i < 5; i++) sc4[i] = hp[i];

        u64 a0 = xa.x, a1 = xa.y, b0 = 0ull, b1 = 0ull;
        #pragma unroll
        for (int k = 0; k < 4; k++){
            u64 s = pack2(sc[k], sc[k]);
            if (k & 1){ b0 = fma2(s, ut[k].x, b0); b1 = fma2(s, ut[k].y, b1); }
            else      { a0 = fma2(s, ut[k].x, a0); a1 = fma2(s, ut[k].y, a1); }
        }
        #pragma unroll
        for (int r = 0; r < RFF; r++){
            u64 s = pack2(sc[4+r], sc[4+r]);
            if (r & 1){ b0 = fma2(s, w2[r].x, b0); b1 = fma2(s, w2[r].y, b1); }
            else      { a0 = fma2(s, w2[r].x, a0); a1 = fma2(s, w2[r].y, a1); }
        }
        ulonglong2 o;
        o.x = add2(a0, b0);
        o.y = add2(a1, b1);
        op[(size_t)row*(DD/4)] = o;
        xa = xn;
    }
}

// ======================= launch =======================
extern "C" void kernel_launch(void* const* d_in, const int* in_sizes, int n_in,
                              void* d_out, int out_size){
    const float* x       = (const float*)d_in[0];
    const float* norm_w  = (const float*)d_in[1];
    const float* V       = (const float*)d_in[2];
    const float* U       = (const float*)d_in[3];
    const float* a_logit = (const float*)d_in[4];
    const float* W1      = (const float*)d_in[5];
    const float* W2      = (const float*)d_in[6];
    float* out = (float*)d_out;

    k_prep_all<<<88, 256>>>(norm_w, V, U, a_logit, W1);
    k_u    <<<NROWS/TRU, 512>>>(x);
    k_scan <<<BB*RR, 256>>>();
    k_post <<<NROWS/256, 256>>>();
    dim3 gm(NROWS/TRM, 2);
    k_main <<<gm, 256>>>(x, W2, out);
}

// round 12
// speedup vs baseline: 1.3199x; 1.0084x over previous
#include <cuda_runtime.h>
#include <cstdint>

#define BB 4
#define SS 4096
#define DD 2048
#define RR 4
#define RFF 16
#define NROWS (BB*SS)   // 16384
#define TRU 8           // rows per block in k_u (2 groups x 4 rows)
#define TRM 16          // rows per block in k_main
#define EPS 1e-6f

typedef unsigned long long u64;

// -------- device scratch (no allocation allowed) --------
__device__ __align__(16) float g_ssq[NROWS];
__device__ __align__(16) float g_u  [RR*NROWS];   // planar [r][row], pre-scaled by rmsnorm
__device__ __align__(16) float g_pu [NROWS*RR];   // row-major
__device__ __align__(16) float g_pw1[NROWS*RFF];  // row-major
__device__ __align__(16) float g_h  [RR*NROWS];   // planar [r][row]
__device__ __align__(16) float g_g  [NROWS*RFF];  // row-major
__device__ __align__(16) float g_Vt [RR*DD];      // w*V transposed
__device__ __align__(16) float g_Ut [RR*DD];      // U transposed
__device__ __align__(16) float g_W1t[RFF*DD];     // w*W1 transposed
__device__ float g_G[16];    // U^T U
__device__ float g_M[64];    // U^T (w*W1)
__device__ float g_a[RR];

// -------- packed f32x2 helpers --------
__device__ __forceinline__ u64 fma2(u64 a, u64 b, u64 c){
    u64 d; asm("fma.rn.f32x2 %0, %1, %2, %3;" : "=l"(d) : "l"(a), "l"(b), "l"(c)); return d;
}
__device__ __forceinline__ u64 add2(u64 a, u64 b){
    u64 d; asm("add.rn.f32x2 %0, %1, %2;" : "=l"(d) : "l"(a), "l"(b)); return d;
}
__device__ __forceinline__ u64 pack2(float x, float y){
    u64 r; asm("mov.b64 %0, {%1, %2};" : "=l"(r) : "f"(x), "f"(y)); return r;
}
__device__ __forceinline__ float2 unpack2(u64 p){
    float2 f; asm("mov.b64 {%0, %1}, %2;" : "=f"(f.x), "=f"(f.y) : "l"(p)); return f;
}
__device__ __forceinline__ float warp_sum(float v){
    v += __shfl_down_sync(0xffffffffu, v, 16);
    v += __shfl_down_sync(0xffffffffu, v, 8);
    v += __shfl_down_sync(0xffffffffu, v, 4);
    v += __shfl_down_sync(0xffffffffu, v, 2);
    v += __shfl_down_sync(0xffffffffu, v, 1);
    return v;
}
// butterfly reduce-scatter: after call, each lane holds warp-total of
// value index (lane & (N-1)). N power of 2.
template<int N>
__device__ __forceinline__ float rs_reduce(float (&v)[N], int lane){
    #pragma unroll
    for (int s = N/2; s >= 1; s >>= 1){
        bool up = (lane & s) != 0;
        #pragma unroll
        for (int i = 0; i < s; i++){
            float send = up ? v[i] : v[i+s];
            float keep = up ? v[i+s] : v[i];
            v[i] = keep + __shfl_xor_sync(0xffffffffu, send, s);
        }
    }
    float r = v[0];
    #pragma unroll
    for (int s = N; s < 32; s <<= 1)
        r += __shfl_xor_sync(0xffffffffu, r, s);
    return r;
}
__device__ __forceinline__ float gelu_tanh(float x){
    float c = 0.7978845608028654f * (x + 0.044715f * x * x * x);
    return 0.5f * x * (1.0f + tanhf(c));
}

// ======================= prep (fused): transpose/fold + G/M dots =======================
__global__ void k_prep_all(const float* __restrict__ norm_w, const float* __restrict__ V,
                           const float* __restrict__ U, const float* __restrict__ a_logit,
                           const float* __restrict__ W1){
    int tid = threadIdx.x;
    if (blockIdx.x < 8){
        int d = blockIdx.x * 256 + tid;
        float w = norm_w[d];
        #pragma unroll
        for (int r = 0; r < RR; r++){
            g_Vt[r*DD + d] = w * V[d*RR + r];
            g_Ut[r*DD + d] = U[d*RR + r];
        }
        #pragma unroll
        for (int r = 0; r < RFF; r++)
            g_W1t[r*DD + d] = w * W1[d*RFF + r];
        if (blockIdx.x == 0 && tid < RR) g_a[tid] = 1.0f / (1.0f + expf(-a_logit[tid]));
    } else {
        int j = blockIdx.x - 8;   // 0..79
        float s = 0.f;
        if (j < 16){
            int k = j >> 2, q = j & 3;
            for (int d = tid; d < DD; d += 256)
                s += U[d*RR + k] * U[d*RR + q];
        } else {
            int k = (j-16) >> 4, r = (j-16) & 15;
            for (int d = tid; d < DD; d += 256)
                s += U[d*RR + k] * norm_w[d] * W1[d*RFF + r];
        }
        s = warp_sum(s);
        __shared__ float sh[8];
        if ((tid & 31) == 0) sh[tid >> 5] = s;
        __syncthreads();
        if (tid == 0){
            float t = 0.f;
            #pragma unroll
            for (int i = 0; i < 8; i++) t += sh[i];
            if (j < 16) g_G[j] = t; else g_M[j-16] = t;
        }
    }
}

// ======================= k_u v2: 8 d's per thread, 2 row-groups =======================
// 512 threads = 2 groups x 256; group g handles rows row0+4g..+3.
// Thread covers d in [8*gt, 8*gt+8). Six 4-dot weight passes; ssq in pass 0.
// Slots: 0=ssq, 1..4=V, 5..8=U, 9..24=W1.
__global__ void __launch_bounds__(512) k_u(const float* __restrict__ x){
    const int tid = threadIdx.x;
    const int g   = tid >> 8;          // group 0/1
    const int gt  = tid & 255;         // thread within group
    const int w8  = gt >> 5;           // warp within group (0..7)
    const int l   = gt & 31;
    const int rowg = blockIdx.x * TRU + g*4;   // first row of this group

    __shared__ float sred[TRU][25][9];
    __shared__ float tot[TRU][25];

    // stage 4 rows x 8 d's in registers
    ulonglong2 xp[4][2];
    #pragma unroll
    for (int i = 0; i < 4; i++){
        const ulonglong2* xr = reinterpret_cast<const ulonglong2*>(x)
                             + (size_t)(rowg+i)*(DD/4) + gt*2;
        xp[i][0] = xr[0];
        xp[i][1] = xr[1];
    }

    // ---- pass 0: ssq + V0..3 ----
    {
        ulonglong2 wp[4][2];
        #pragma unroll
        for (int j = 0; j < 4; j++){
            wp[j][0] = reinterpret_cast<const ulonglong2*>(g_Vt)[j*(DD/4) + gt*2];
            wp[j][1] = reinterpret_cast<const ulonglong2*>(g_Vt)[j*(DD/4) + gt*2 + 1];
        }
        #pragma unroll
        for (int i = 0; i < 4; i++){
            u64 s = fma2(xp[i][0].x, xp[i][0].x,
                    fma2(xp[i][0].y, xp[i][0].y,
                    fma2(xp[i][1].x, xp[i][1].x,
                    fma2(xp[i][1].y, xp[i][1].y, 0ull))));
            float2 fs = unpack2(s);
            float ss = warp_sum(fs.x + fs.y);
            float p[4];
            #pragma unroll
            for (int j = 0; j < 4; j++){
                u64 a = fma2(xp[i][0].x, wp[j][0].x,
                        fma2(xp[i][0].y, wp[j][0].y,
                        fma2(xp[i][1].x, wp[j][1].x,
                        fma2(xp[i][1].y, wp[j][1].y, 0ull))));
                float2 f = unpack2(a);
                p[j] = f.x + f.y;
            }
            float rv = rs_reduce<4>(p, l);
            int ri = g*4 + i;
            if (l == 0) sred[ri][0][w8] = ss;
            if (l < 4)  sred[ri][1+l][w8] = rv;
        }
    }
    __syncthreads();   // scheduler fence between weight passes

    // ---- passes 1..5: U (slots 5..8) and W1 quads (slots 9..24) ----
    #pragma unroll
    for (int pass = 1; pass < 6; pass++){
        const float* wsrc = (pass == 1) ? g_Ut : (g_W1t + (pass-2)*4*DD);
        const int slot0   = (pass == 1) ? 5 : (9 + (pass-2)*4);
        ulonglong2 wp[4][2];
        #pragma unroll
        for (int j = 0; j < 4; j++){
            wp[j][0] = reinterpret_cast<const ulonglong2*>(wsrc)[j*(DD/4) + gt*2];
            wp[j][1] = reinterpret_cast<const ulonglong2*>(wsrc)[j*(DD/4) + gt*2 + 1];
        }
        #pragma unroll
        for (int i = 0; i < 4; i++){
            float p[4];
            #pragma unroll
            for (int j = 0; j < 4; j++){
                u64 a = fma2(xp[i][0].x, wp[j][0].x,
                        fma2(xp[i][0].y, wp[j][0].y,
                        fma2(xp[i][1].x, wp[j][1].x,
                        fma2(xp[i][1].y, wp[j][1].y, 0ull))));
                float2 f = unpack2(a);
                p[j] = f.x + f.y;
            }
            float rv = rs_reduce<4>(p, l);
            int ri = g*4 + i;
            if (l < 4) sred[ri][slot0+l][w8] = rv;
        }
        __syncthreads();
    }

    // ---- cross-warp reduce (8 warp-partials) + scatter ----
    if (tid < TRU*25){
        int row = tid / 25, val = tid % 25;
        float s = 0.f;
        #pragma unroll
        for (int ww = 0; ww < 8; ww++) s += sred[row][val][ww];
        tot[row][val] = s;
    }
    __syncthreads();
    if (tid < TRU*25){
        int row = tid / 25, val = tid % 25;
        int gr = blockIdx.x * TRU + row;
        float s = tot[row][val];
        if (val == 0) g_ssq[gr] = s;
        else if (val < 5){
            float scale = rsqrtf(tot[row][0] * (1.0f/DD) + EPS);
            g_u[(val-1)*NROWS + gr] = scale * s;
        }
        else if (val < 9) g_pu[(size_t)gr*RR + (val-5)] = s;
        else              g_pw1[(size_t)gr*RFF + (val-9)] = s;
    }
}

// ======================= k_scan: warp-parallel linear-recurrence scan =======================
__global__ void __launch_bounds__(256) k_scan(){
    const int b = blockIdx.x >> 2;
    const int r = blockIdx.x & 3;
    const float a = g_a[r];
    const int tid = threadIdx.x, l = tid & 31, w = tid >> 5;
    const float* u = g_u + r*NROWS + b*SS;

    float uu[16];
    float4* uu4 = reinterpret_cast<float4*>(uu);
    #pragma unroll
    for (int i = 0; i < 4; i++)
        uu4[i] = reinterpret_cast<const float4*>(u)[tid*4 + i];

    float f = 0.f;
    #pragma unroll
    for (int i = 0; i < 16; i++) f = a*f + uu[i];

    float A = a; A *= A; A *= A; A *= A; A *= A;   // a^16

    float I = f, As = A;
    #pragma unroll
    for (int st = 0; st < 5; st++){
        float gg = __shfl_up_sync(0xffffffffu, I, 1 << st);
        if (l >= (1 << st)) I += As * gg;
        As *= As;
    }

    __shared__ float Tw[8], Ww[8];
    if (l == 31) Tw[w] = I;
    __syncthreads();
    if (tid == 0){
        float A32 = A;
        #pragma unroll
        for (int k = 0; k < 5; k++) A32 *= A32;  // a^512
        float c = 0.f;
        #pragma unroll
        for (int j = 0; j < 8; j++){ Ww[j] = c; c = A32*c + Tw[j]; }
    }
    __syncthreads();

    float Al = 1.f, p = A;
    #pragma unroll
    for (int bit = 0; bit < 5; bit++){ if ((l >> bit) & 1) Al *= p; p *= p; }
    float Iprev = __shfl_up_sync(0xffffffffu, I, 1);
    float c = ((l == 0) ? 0.f : Iprev) + Al * Ww[w];

    float* hh = g_h + r*NROWS + b*SS;
    float h = c;
    float ho[16];
    #pragma unroll
    for (int i = 0; i < 16; i++){ h = a*h + uu[i]; ho[i] = h; }
    float4* ho4 = reinterpret_cast<float4*>(ho);
    #pragma unroll
    for (int i = 0; i < 4; i++)
        reinterpret_cast<float4*>(hh)[tid*4 + i] = ho4[i];
}

// ======================= k_post: per-row scale1, t, gelu =======================
__global__ void __launch_bounds__(256) k_post(){
    __shared__ float sG[16], sM[64];
    int tid = threadIdx.x;
    if (tid < 16) sG[tid] = g_G[tid];
    if (tid < 64) sM[tid] = g_M[tid];
    __syncthreads();

    int row = blockIdx.x * 256 + tid;
    float h[4], p[4];
    #pragma unroll
    for (int k = 0; k < 4; k++) h[k] = g_h[k*NROWS + row];
    float4 p4 = reinterpret_cast<const float4*>(g_pu)[row];
    p[0]=p4.x; p[1]=p4.y; p[2]=p4.z; p[3]=p4.w;

    float s1 = g_ssq[row];
    #pragma unroll
    for (int k = 0; k < 4; k++) s1 += 2.0f * h[k] * p[k];
    #pragma unroll
    for (int k = 0; k < 4; k++)
        #pragma unroll
        for (int q = 0; q < 4; q++) s1 += h[k] * h[q] * sG[k*4+q];
    float scale = rsqrtf(s1 * (1.0f/DD) + EPS);

    #pragma unroll
    for (int r = 0; r < RFF; r++){
        float t = g_pw1[(size_t)row*RFF + r];
        #pragma unroll
        for (int k = 0; k < 4; k++) t += h[k] * sM[k*16 + r];
        g_g[(size_t)row*RFF + r] = gelu_tanh(t * scale);
    }
}

// ======================= k_main: out = x + U h + g @ W2 (R7 exact, TRM=16) =======================
__global__ void __launch_bounds__(256, 2) k_main(const float* __restrict__ x,
                                                 const float* __restrict__ W2,
                                                 float* __restrict__ out){
    const int row0 = blockIdx.x * TRM;
    const int tid  = threadIdx.x;
    const int q    = blockIdx.y * 256 + tid;   // ulonglong2 index within row (0..511)

    ulonglong2 ut[4], w2[16];
    #pragma unroll
    for (int k = 0; k < 4; k++)
        ut[k] = reinterpret_cast<const ulonglong2*>(g_Ut)[k*(DD/4) + q];
    #pragma unroll
    for (int r = 0; r < RFF; r++)
        w2[r] = reinterpret_cast<const ulonglong2*>(W2)[r*(DD/4) + q];

    __shared__ __align__(16) float hs[TRM][20];
    for (int i = tid; i < TRM*20; i += 256){
        int row = i / 20, j = i % 20;
        hs[row][j] = (j < 4) ? g_h[j*NROWS + row0 + row]
                             : g_g[(size_t)(row0+row)*RFF + (j-4)];
    }
    __syncthreads();

    const ulonglong2* xr = reinterpret_cast<const ulonglong2*>(x) + (size_t)row0*(DD/4) + q;
    ulonglong2*       op = reinterpret_cast<ulonglong2*>(out)     + (size_t)row0*(DD/4) + q;

    ulonglong2 xa = xr[0];
    #pragma unroll
    for (int row = 0; row < TRM; row++){
        ulonglong2 xn = xa;
        if (row + 1 < TRM) xn = xr[(size_t)(row+1)*(DD/4)];

        float sc[20];
        float4* sc4 = reinterpret_cast<float4*>(sc);
        const float4* hp = reinterpret_cast<const float4*>(&hs[row][0]);
        #pragma unroll
        for (int i = 0; i < 5; i++) sc4[i] = hp[i];

        u64 a0 = xa.x, a1 = xa.y, b0 = 0ull, b1 = 0ull;
        #pragma unroll
        for (int k = 0; k < 4; k++){
            u64 s = pack2(sc[k], sc[k]);
            if (k & 1){ b0 = fma2(s, ut[k].x, b0); b1 = fma2(s, ut[k].y, b1); }
            else      { a0 = fma2(s, ut[k].x, a0); a1 = fma2(s, ut[k].y, a1); }
        }
        #pragma unroll
        for (int r = 0; r < RFF; r++){
            u64 s = pack2(sc[4+r], sc[4+r]);
            if (r & 1){ b0 = fma2(s, w2[r].x, b0); b1 = fma2(s, w2[r].y, b1); }
            else      { a0 = fma2(s, w2[r].x, a0); a1 = fma2(s, w2[r].y, a1); }
        }
        ulonglong2 o;
        o.x = add2(a0, b0);
        o.y = add2(a1, b1);
        op[(size_t)row*(DD/4)] = o;
        xa = xn;
    }
}

// ======================= launch =======================
extern "C" void kernel_launch(void* const* d_in, const int* in_sizes, int n_in,
                              void* d_out, int out_size){
    const float* x       = (const float*)d_in[0];
    const float* norm_w  = (const float*)d_in[1];
    const float* V       = (const float*)d_in[2];
    const float* U       = (const float*)d_in[3];
    const float* a_logit = (const float*)d_in[4];
    const float* W1      = (const float*)d_in[5];
    const float* W2      = (const float*)d_in[6];
    float* out = (float*)d_out;

    k_prep_all<<<88, 256>>>(norm_w, V, U, a_logit, W1);
    k_u    <<<NROWS/TRU, 512>>>(x);
    k_scan <<<BB*RR, 256>>>();
    k_post <<<NROWS/256, 256>>>();
    dim3 gm(NROWS/TRM, 2);
    k_main <<<gm, 256>>>(x, W2, out);
}